// round 16
// baseline (speedup 1.0000x reference)
#include <cuda_runtime.h>
#include <math.h>

#define NPTS 4096
#define BATCH 8
#define EPS 1e-5f
#define NQ 8
#define MQ (NPTS / NQ)
#define NCTAS 512

// scratch (fully rewritten every launch -> graph-replay deterministic)
__device__ float g_feat1[BATCH * 73728];
__device__ float g_pmax[BATCH * 192 * 16];     // [(b*192 + o*3+kk)*16 + ch]
__device__ float g_ps[3][NQ * BATCH * NPTS];
__device__ int   g_pi[3][NQ * BATCH * NPTS];
__device__ float g_P[BATCH][128];              // padded row (128B-line aligned)
__device__ float g_HA[BATCH][256];
__device__ float g_HB[BATCH][128];

// device-wide sense-reversing barrier state (returns to {0,0} every launch)
__device__ int g_count = 0;
__device__ volatile int g_sense = 0;

struct Top3 { float s0, s1, s2; int i0, i1, i2; };

__device__ __forceinline__ void top3_insert(Top3& t, float s, int m) {
    if (s > t.s2) {
        if (s > t.s1) {
            t.s2 = t.s1; t.i2 = t.i1;
            if (s > t.s0) { t.s1 = t.s0; t.i1 = t.i0; t.s0 = s; t.i0 = m; }
            else { t.s1 = s; t.i1 = m; }
        } else { t.s2 = s; t.i2 = m; }
    }
}

__device__ __forceinline__ void grid_bar(int& ls) {
    __syncthreads();
    if (threadIdx.x == 0) {
        ls ^= 1;
        __threadfence();
        if (atomicAdd(&g_count, 1) == NCTAS - 1) {
            g_count = 0;
            __threadfence();
            g_sense = ls;
        } else {
            while (g_sense != ls) { }
        }
        __threadfence();
    }
    __syncthreads();
}

struct TailSm {
    float X1[192], F2[1152], X2[18], F3[108], X3[18], F4[108], X4[18];
    float P[82], LG[3];
    float red[4][64];
};
union Smem {
    float4 ym[MQ];
    TailSm t;
};

__device__ __forceinline__ void small_knn6(const float* Xin, float* F, int n) {
    float a0 = Xin[n], a1 = Xin[6 + n], a2 = Xin[12 + n];
    Top3 t; t.s0 = t.s1 = t.s2 = -INFINITY; t.i0 = t.i1 = t.i2 = 0;
    for (int m = 0; m < 6; m++) {
        float z0 = Xin[m], z1 = Xin[6 + m], z2 = Xin[12 + m];
        float s = 2.0f * (a0 * z0 + a1 * z1 + a2 * z2) - (z0 * z0 + z1 * z1 + z2 * z2);
        top3_insert(t, s, m);
    }
    int idx3[3] = { t.i0, t.i1, t.i2 };
    for (int kk = 0; kk < 3; kk++) {
        int m = idx3[kk];
        for (int c = 0; c < 3; c++) {
            F[n * 18 + kk * 6 + c] = Xin[m * 3 + c] - Xin[n * 3 + c];
            F[n * 18 + kk * 6 + 3 + c] = Xin[n * 3 + c];
        }
    }
}

__global__ void __launch_bounds__(256, 4)
fused_kernel(const float* __restrict__ x,  const float* __restrict__ w1,
             const float* __restrict__ wA, const float* __restrict__ bA,
             const float* __restrict__ wB, const float* __restrict__ bB,
             const float* __restrict__ wC, const float* __restrict__ bC,
             const float* __restrict__ bn1g, const float* __restrict__ bn1b,
             const float* __restrict__ bn1m, const float* __restrict__ bn1v,
             const float* __restrict__ bnAg, const float* __restrict__ bnAb,
             const float* __restrict__ bnAm, const float* __restrict__ bnAv,
             const float* __restrict__ bnBg, const float* __restrict__ bnBb,
             const float* __restrict__ bnBm, const float* __restrict__ bnBv,
             float* __restrict__ out) {
    __shared__ Smem sm;
    int cta = blockIdx.x, tid = threadIdx.x;
    int warp = tid >> 5, lane = tid & 31;
    int ls = 0;   // barrier sense (6 barriers -> even -> replay-safe)

    // ================= P1: partial kNN scan (512 CTAs, R11-proven config) ====
    {
        int nc = cta & 7, b = (cta >> 3) & 7, q = cta >> 6;
        const float* raw = x + (size_t)b * 3 * NPTS;
        int mbase = q * MQ;
        for (int m = tid; m < MQ; m += 256) {
            int mg = mbase + m;
            float y0 = raw[mg], y1 = raw[NPTS + mg], y2 = raw[2 * NPTS + mg];
            sm.ym[m] = make_float4(y0, y1, y2, -(y0 * y0 + y1 * y1 + y2 * y2));
        }
        __syncthreads();

        int n0 = nc * 512 + tid, n1 = n0 + 256;
        float a0 = 2.0f * raw[n0], a1 = 2.0f * raw[NPTS + n0], a2 = 2.0f * raw[2 * NPTS + n0];
        float c0 = 2.0f * raw[n1], c1 = 2.0f * raw[NPTS + n1], c2 = 2.0f * raw[2 * NPTS + n1];
        Top3 ta; ta.s0 = ta.s1 = ta.s2 = -INFINITY; ta.i0 = ta.i1 = ta.i2 = 0;
        Top3 tb = ta;
#pragma unroll 8
        for (int m = 0; m < MQ; m++) {
            float4 p = sm.ym[m];
            float sa = fmaf(a0, p.x, fmaf(a1, p.y, fmaf(a2, p.z, p.w)));
            float sb = fmaf(c0, p.x, fmaf(c1, p.y, fmaf(c2, p.z, p.w)));
            top3_insert(ta, sa, mbase + m);
            top3_insert(tb, sb, mbase + m);
        }
        int off0 = (q * BATCH + b) * NPTS + n0, off1 = off0 + 256;
        g_ps[0][off0] = ta.s0; g_ps[1][off0] = ta.s1; g_ps[2][off0] = ta.s2;
        g_pi[0][off0] = ta.i0; g_pi[1][off0] = ta.i1; g_pi[2][off0] = ta.i2;
        g_ps[0][off1] = tb.s0; g_ps[1][off1] = tb.s1; g_ps[2][off1] = tb.s2;
        g_pi[0][off1] = tb.i0; g_pi[1][off1] = tb.i1; g_pi[2][off1] = tb.i2;
    }
    grid_bar(ls);   // B1

    // ================= P2: merge NQ partials + build feature_src (CTAs<128) ==
    if (cta < 128) {
        int b = cta >> 4;
        int n = (cta & 15) * 256 + tid;
        const float* raw = x + (size_t)b * 3 * NPTS;
        Top3 t; t.s0 = t.s1 = t.s2 = -INFINITY; t.i0 = t.i1 = t.i2 = 0;
#pragma unroll
        for (int q = 0; q < NQ; q++) {
            int off = (q * BATCH + b) * NPTS + n;
#pragma unroll
            for (int r = 0; r < 3; r++)
                top3_insert(t, __ldcg(&g_ps[r][off]), __ldcg(&g_pi[r][off]));
        }
        float sx0 = raw[n * 3 + 0], sx1 = raw[n * 3 + 1], sx2 = raw[n * 3 + 2];
        float2* fo2 = reinterpret_cast<float2*>(g_feat1 + (size_t)b * 73728 + n * 18);
        int idx3[3] = { t.i0, t.i1, t.i2 };
#pragma unroll
        for (int kk = 0; kk < 3; kk++) {
            int m = idx3[kk];
            float d0 = raw[m * 3 + 0] - sx0;
            float d1 = raw[m * 3 + 1] - sx1;
            float d2 = raw[m * 3 + 2] - sx2;
            fo2[kk * 3 + 0] = make_float2(d0, d1);
            fo2[kk * 3 + 1] = make_float2(d2, sx0);
            fo2[kk * 3 + 2] = make_float2(sx1, sx2);
        }
    }
    grid_bar(ls);   // B2

    // ================= P3: conv1 + BN + lrelu + partial max (CTAs<384) =======
    if (cta < 384) {
        int b = cta / 48, rem = cta % 48, kk = rem / 16, ch = rem % 16;
        int o = tid & 63, sub = tid >> 6;
        float s = bn1g[o] / sqrtf(bn1v[o] + EPS);
        float w0 = w1[o * 6 + 0] * s, w1_ = w1[o * 6 + 1] * s, w2 = w1[o * 6 + 2] * s;
        float w3 = w1[o * 6 + 3] * s, w4 = w1[o * 6 + 4] * s, w5 = w1[o * 6 + 5] * s;
        float be = bn1b[o] - bn1m[o] * s;
        const float* f = g_feat1 + (size_t)b * 73728 + kk * 4096 + ch * 256 + sub * 64;
        float mx = -INFINITY;
#pragma unroll 4
        for (int n2 = 0; n2 < 64; n2++) {
            float acc = be;
            acc = fmaf(w0, __ldcg(&f[n2]), acc);
            acc = fmaf(w1_, __ldcg(&f[12288 + n2]), acc);
            acc = fmaf(w2, __ldcg(&f[2 * 12288 + n2]), acc);
            acc = fmaf(w3, __ldcg(&f[3 * 12288 + n2]), acc);
            acc = fmaf(w4, __ldcg(&f[4 * 12288 + n2]), acc);
            acc = fmaf(w5, __ldcg(&f[5 * 12288 + n2]), acc);
            float v = fmaxf(acc, 0.2f * acc);
            mx = fmaxf(mx, v);
        }
        __syncthreads();   // protect union vs P2 smem (none used) & red reuse
        sm.t.red[sub][o] = mx;
        __syncthreads();
        if (sub == 0) {
            float r = fmaxf(fmaxf(sm.t.red[0][o], sm.t.red[1][o]),
                            fmaxf(sm.t.red[2][o], sm.t.red[3][o]));
            g_pmax[(b * 192 + o * 3 + kk) * 16 + ch] = r;
        }
    }
    grid_bar(ls);   // B3

    // ====== P4: x1 reduce + stages 2-4 + pool per batch (CTAs 0-7) ===========
    if (cta < 8) {
        int b = cta, t = tid;
        if (t < 192) {
            const float4* pm = reinterpret_cast<const float4*>(&g_pmax[(b * 192 + t) * 16]);
            float4 v0 = __ldcg(pm + 0), v1 = __ldcg(pm + 1);
            float4 v2 = __ldcg(pm + 2), v3 = __ldcg(pm + 3);
            float m0 = fmaxf(fmaxf(v0.x, v0.y), fmaxf(v0.z, v0.w));
            float m1 = fmaxf(fmaxf(v1.x, v1.y), fmaxf(v1.z, v1.w));
            float m2 = fmaxf(fmaxf(v2.x, v2.y), fmaxf(v2.z, v2.w));
            float m3 = fmaxf(fmaxf(v3.x, v3.y), fmaxf(v3.z, v3.w));
            sm.t.X1[t] = fmaxf(fmaxf(m0, m1), fmaxf(m2, m3));
        }
        __syncthreads();
        if (t < 64) {
            int n = t;
            float a0 = sm.t.X1[n], a1 = sm.t.X1[64 + n], a2 = sm.t.X1[128 + n];
            Top3 tp; tp.s0 = tp.s1 = tp.s2 = -INFINITY; tp.i0 = tp.i1 = tp.i2 = 0;
            for (int m = 0; m < 64; m++) {
                float z0 = sm.t.X1[m], z1 = sm.t.X1[64 + m], z2 = sm.t.X1[128 + m];
                float s = 2.0f * (a0 * z0 + a1 * z1 + a2 * z2) - (z0 * z0 + z1 * z1 + z2 * z2);
                top3_insert(tp, s, m);
            }
            int idx3[3] = { tp.i0, tp.i1, tp.i2 };
            for (int kk = 0; kk < 3; kk++) {
                int m = idx3[kk];
                for (int c = 0; c < 3; c++) {
                    sm.t.F2[n * 18 + kk * 6 + c] = sm.t.X1[m * 3 + c] - sm.t.X1[n * 3 + c];
                    sm.t.F2[n * 18 + kk * 6 + 3 + c] = sm.t.X1[n * 3 + c];
                }
            }
        }
        __syncthreads();
        if (t < 18) {
            float mx = -INFINITY;
            for (int j = 0; j < 64; j++) mx = fmaxf(mx, sm.t.F2[t * 64 + j]);
            sm.t.X2[t] = mx;
        }
        __syncthreads();
        if (t < 6) small_knn6(sm.t.X2, sm.t.F3, t);
        __syncthreads();
        if (t < 18) {
            float mx = -INFINITY;
            for (int j = 0; j < 6; j++) mx = fmaxf(mx, sm.t.F3[t * 6 + j]);
            sm.t.X3[t] = mx;
        }
        __syncthreads();
        if (t < 6) small_knn6(sm.t.X3, sm.t.F4, t);
        __syncthreads();
        if (t < 18) {
            float mx = -INFINITY;
            for (int j = 0; j < 6; j++) mx = fmaxf(mx, sm.t.F4[t * 6 + j]);
            sm.t.X4[t] = mx;
        }
        __syncthreads();
        if (t < 82) {
            float mx;
            if (t < 64)      mx = fmaxf(fmaxf(sm.t.X1[t * 3], sm.t.X1[t * 3 + 1]), sm.t.X1[t * 3 + 2]);
            else if (t < 70) { int c = t - 64; mx = fmaxf(fmaxf(sm.t.X2[c * 3], sm.t.X2[c * 3 + 1]), sm.t.X2[c * 3 + 2]); }
            else if (t < 76) { int c = t - 70; mx = fmaxf(fmaxf(sm.t.X3[c * 3], sm.t.X3[c * 3 + 1]), sm.t.X3[c * 3 + 2]); }
            else             { int c = t - 76; mx = fmaxf(fmaxf(sm.t.X4[c * 3], sm.t.X4[c * 3 + 1]), sm.t.X4[c * 3 + 2]); }
            g_P[b][t] = mx;
        }
    }
    grid_bar(ls);   // B4

    // ================= P5: MLP A 82->256 spread over all warps ===============
    {
        int gw = cta * 8 + warp;          // 4096 warps, 2048 tasks
        if (gw < 2048) {
            int b = gw >> 8, j = gw & 255;
            const float* wr = wA + j * 82;
            float acc = g_P[b][lane] * wr[lane];
            acc = fmaf(g_P[b][lane + 32], wr[lane + 32], acc);
            if (lane < 18) acc = fmaf(g_P[b][lane + 64], wr[lane + 64], acc);
#pragma unroll
            for (int d = 16; d > 0; d >>= 1)
                acc += __shfl_xor_sync(0xFFFFFFFFu, acc, d);
            if (lane == 0) {
                acc += bA[j];
                float s = bnAg[j] / sqrtf(bnAv[j] + EPS);
                acc = (acc - bnAm[j]) * s + bnAb[j];
                g_HA[b][j] = fmaxf(acc, 0.2f * acc);
            }
        }
    }
    grid_bar(ls);   // B5

    // ================= P6: MLP B 256->128 spread over warps ==================
    {
        int gw = cta * 8 + warp;          // 1024 tasks
        if (gw < 1024) {
            int b = gw >> 7, j = gw & 127;
            const float* wr = wB + j * 256;
            float a0 = __ldcg(&g_HA[b][lane]) * wr[lane];
            float a1 = __ldcg(&g_HA[b][lane + 32]) * wr[lane + 32];
#pragma unroll
            for (int e = 2; e < 8; e += 2) {
                a0 = fmaf(__ldcg(&g_HA[b][lane + 32 * e]), wr[lane + 32 * e], a0);
                a1 = fmaf(__ldcg(&g_HA[b][lane + 32 * (e + 1)]), wr[lane + 32 * (e + 1)], a1);
            }
            float acc = a0 + a1;
#pragma unroll
            for (int d = 16; d > 0; d >>= 1)
                acc += __shfl_xor_sync(0xFFFFFFFFu, acc, d);
            if (lane == 0) {
                acc += bB[j];
                float s = bnBg[j] / sqrtf(bnBv[j] + EPS);
                acc = (acc - bnBm[j]) * s + bnBb[j];
                g_HB[b][j] = fmaxf(acc, 0.2f * acc);
            }
        }
    }
    grid_bar(ls);   // B6 (6 barriers total: even -> sense restored)

    // ================= P7: MLP C + softmax (CTAs 0-7) ========================
    if (cta < 8) {
        int b = cta, t = tid;
        if (t < 96) {
            int o = warp, l = lane;
            float acc = 0.0f;
#pragma unroll
            for (int e = 0; e < 4; e++) {
                int i = l + 32 * e;
                acc = fmaf(__ldcg(&g_HB[b][i]), wC[o * 128 + i], acc);
            }
#pragma unroll
            for (int d = 16; d > 0; d >>= 1)
                acc += __shfl_xor_sync(0xFFFFFFFFu, acc, d);
            if (l == 0) sm.t.LG[o] = acc + bC[o];
        }
        __syncthreads();
        if (t == 0) {
            float m = fmaxf(fmaxf(sm.t.LG[0], sm.t.LG[1]), sm.t.LG[2]);
            float e0 = expf(sm.t.LG[0] - m), e1 = expf(sm.t.LG[1] - m), e2 = expf(sm.t.LG[2] - m);
            float inv = 1.0f / (e0 + e1 + e2);
            out[b * 3 + 0] = e0 * inv;
            out[b * 3 + 1] = e1 * inv;
            out[b * 3 + 2] = e2 * inv;
        }
    }
}

// ---------------------------------------------------------------------------
extern "C" void kernel_launch(void* const* d_in, const int* in_sizes, int n_in,
                              void* d_out, int out_size) {
    const float* x   = (const float*)d_in[0];
    const float* w1  = (const float*)d_in[1];
    const float* wA  = (const float*)d_in[2];
    const float* bA  = (const float*)d_in[3];
    const float* wB  = (const float*)d_in[4];
    const float* bB  = (const float*)d_in[5];
    const float* wC  = (const float*)d_in[6];
    const float* bC  = (const float*)d_in[7];
    const float* bn1g = (const float*)d_in[8];
    const float* bn1b = (const float*)d_in[9];
    const float* bn1m = (const float*)d_in[10];
    const float* bn1v = (const float*)d_in[11];
    const float* bnAg = (const float*)d_in[12];
    const float* bnAb = (const float*)d_in[13];
    const float* bnAm = (const float*)d_in[14];
    const float* bnAv = (const float*)d_in[15];
    const float* bnBg = (const float*)d_in[16];
    const float* bnBb = (const float*)d_in[17];
    const float* bnBm = (const float*)d_in[18];
    const float* bnBv = (const float*)d_in[19];

    fused_kernel<<<NCTAS, 256>>>(x, w1, wA, bA, wB, bB, wC, bC,
                                 bn1g, bn1b, bn1m, bn1v,
                                 bnAg, bnAb, bnAm, bnAv,
                                 bnBg, bnBb, bnBm, bnBv,
                                 (float*)d_out);
}

// round 17
// speedup vs baseline: 1.1171x; 1.1171x over previous
#include <cuda_runtime.h>
#include <math.h>

#define NPTS 4096
#define BATCH 8
#define EPS 1e-5f
#define NQ 8            // m-dimension split
#define MQ (NPTS / NQ)  // 512 points per slice

// scratch (fully rewritten every launch -> graph-replay deterministic)
__device__ float g_feat1[BATCH * 73728];           // (B, N*18) feature_src flat
__device__ float4 g_pmax4[BATCH * 192 * 4];        // [b*192 + (o*3+kk)][16 ch] as 4 float4
__device__ float g_ps[3][NQ * BATCH * NPTS];       // partial top-3 scores [rank][(q*B+b)*N+n]
__device__ int   g_pi[3][NQ * BATCH * NPTS];       // partial top-3 indices

struct Top3 { float s0, s1, s2; int i0, i1, i2; };

__device__ __forceinline__ void top3_insert(Top3& t, float s, int m) {
    if (s > t.s2) {
        if (s > t.s1) {
            t.s2 = t.s1; t.i2 = t.i1;
            if (s > t.s0) { t.s1 = t.s0; t.i1 = t.i0; t.s0 = s; t.i0 = m; }
            else { t.s1 = s; t.i1 = m; }
        } else { t.s2 = s; t.i2 = m; }
    }
}

// PDL primitives (sm_90+): let dependents launch early / wait for producer data
__device__ __forceinline__ void pdl_launch_dependents() {
    asm volatile("griddepcontrol.launch_dependents;" ::: "memory");
}
__device__ __forceinline__ void pdl_wait() {
    asm volatile("griddepcontrol.wait;" ::: "memory");
}

// ---------------------------------------------------------------------------
// Kernel 1a: partial kNN over one m-slice, 2 queries per thread (R11 config)
// grid (8 nchunk, 8 batch, NQ slice), block 256, 8KB static smem
// ---------------------------------------------------------------------------
__global__ void knn_partial_kernel(const float* __restrict__ x) {
    pdl_launch_dependents();   // let merge kernel begin its launch/prelude
    __shared__ float4 ym[MQ];  // (y0,y1,y2,-||y||^2), scrambled view, this slice
    int b = blockIdx.y, q = blockIdx.z;
    const float* raw = x + (size_t)b * 3 * NPTS;
    int mbase = q * MQ;

    for (int m = threadIdx.x; m < MQ; m += blockDim.x) {
        int mg = mbase + m;
        float y0 = raw[mg], y1 = raw[NPTS + mg], y2 = raw[2 * NPTS + mg];
        ym[m] = make_float4(y0, y1, y2, -(y0 * y0 + y1 * y1 + y2 * y2));
    }
    __syncthreads();

    int n0 = blockIdx.x * 512 + threadIdx.x;
    int n1 = n0 + 256;
    // fold the factor 2 into query coords: s = 2*dot(y_n,y_m) - ||y_m||^2
    float a0 = 2.0f * raw[n0], a1 = 2.0f * raw[NPTS + n0], a2 = 2.0f * raw[2 * NPTS + n0];
    float c0 = 2.0f * raw[n1], c1 = 2.0f * raw[NPTS + n1], c2 = 2.0f * raw[2 * NPTS + n1];
    Top3 ta; ta.s0 = ta.s1 = ta.s2 = -INFINITY; ta.i0 = ta.i1 = ta.i2 = 0;
    Top3 tb; tb.s0 = tb.s1 = tb.s2 = -INFINITY; tb.i0 = tb.i1 = tb.i2 = 0;

#pragma unroll 8
    for (int m = 0; m < MQ; m++) {
        float4 p = ym[m];   // warp-uniform -> LDS broadcast
        float sa = fmaf(a0, p.x, fmaf(a1, p.y, fmaf(a2, p.z, p.w)));
        float sb = fmaf(c0, p.x, fmaf(c1, p.y, fmaf(c2, p.z, p.w)));
        top3_insert(ta, sa, mbase + m);
        top3_insert(tb, sb, mbase + m);
    }

    int off0 = (q * BATCH + b) * NPTS + n0;
    int off1 = off0 + 256;
    g_ps[0][off0] = ta.s0; g_ps[1][off0] = ta.s1; g_ps[2][off0] = ta.s2;
    g_pi[0][off0] = ta.i0; g_pi[1][off0] = ta.i1; g_pi[2][off0] = ta.i2;
    g_ps[0][off1] = tb.s0; g_ps[1][off1] = tb.s1; g_ps[2][off1] = tb.s2;
    g_pi[0][off1] = tb.i0; g_pi[1][off1] = tb.i1; g_pi[2][off1] = tb.i2;
}

// ---------------------------------------------------------------------------
// Kernel 1b: merge NQ partial top-3s + build feature_src (float2 stores)
// grid (16, 8), block 256, PDL-dependent on knn_partial
// ---------------------------------------------------------------------------
__global__ void knn_merge_kernel(const float* __restrict__ x) {
    pdl_launch_dependents();   // let conv kernel begin its launch/prelude
    int b = blockIdx.y;
    int n = blockIdx.x * blockDim.x + threadIdx.x;
    const float* raw = x + (size_t)b * 3 * NPTS;

    // independent prelude: self coords (input x, not produced by predecessor)
    float sx0 = raw[n * 3 + 0], sx1 = raw[n * 3 + 1], sx2 = raw[n * 3 + 2];

    pdl_wait();                // g_ps/g_pi now visible

    Top3 t; t.s0 = t.s1 = t.s2 = -INFINITY; t.i0 = t.i1 = t.i2 = 0;
    // ascending q, ascending rank: strict-> insert keeps lowest index on ties
#pragma unroll
    for (int q = 0; q < NQ; q++) {
        int off = (q * BATCH + b) * NPTS + n;
#pragma unroll
        for (int r = 0; r < 3; r++)
            top3_insert(t, g_ps[r][off], g_pi[r][off]);
    }

    // feature_src[n, kk, 0..5] using ORIGINAL (N,3) interpretation of memory
    float2* fo2 = reinterpret_cast<float2*>(g_feat1 + (size_t)b * 73728 + n * 18);
    int idx3[3] = { t.i0, t.i1, t.i2 };
#pragma unroll
    for (int kk = 0; kk < 3; kk++) {
        int m = idx3[kk];
        float d0 = raw[m * 3 + 0] - sx0;
        float d1 = raw[m * 3 + 1] - sx1;
        float d2 = raw[m * 3 + 2] - sx2;
        fo2[kk * 3 + 0] = make_float2(d0, d1);
        fo2[kk * 3 + 1] = make_float2(d2, sx0);
        fo2[kk * 3 + 2] = make_float2(sx1, sx2);
    }
}

// ---------------------------------------------------------------------------
// Kernel 2: conv1(6->64) folded BN + leaky relu + partial max over n
// grid 384, block 256, PDL-dependent on merge
// ---------------------------------------------------------------------------
__global__ void conv_max_kernel(const float* __restrict__ w1,
                                const float* __restrict__ g,
                                const float* __restrict__ bb,
                                const float* __restrict__ mm,
                                const float* __restrict__ vv) {
    pdl_launch_dependents();   // let tail kernel begin its weight prefetch
    __shared__ float red[4][64];
    int bid = blockIdx.x;
    int b = bid / 48, rem = bid % 48, kk = rem / 16, ch = rem % 16;
    int o = threadIdx.x & 63, sub = threadIdx.x >> 6;

    // independent prelude: fold BN into conv weights (inputs, not produced)
    float s = g[o] / sqrtf(vv[o] + EPS);
    float w0 = w1[o * 6 + 0] * s, w1_ = w1[o * 6 + 1] * s, w2 = w1[o * 6 + 2] * s;
    float w3 = w1[o * 6 + 3] * s, w4 = w1[o * 6 + 4] * s, w5 = w1[o * 6 + 5] * s;
    float be = bb[o] - mm[o] * s;

    pdl_wait();                // g_feat1 now visible

    const float* f = g_feat1 + (size_t)b * 73728 + kk * 4096 + ch * 256 + sub * 64;
    float mx = -INFINITY;
#pragma unroll 4
    for (int n2 = 0; n2 < 64; n2++) {
        float acc = be;
        acc = fmaf(w0, f[n2], acc);
        acc = fmaf(w1_, f[12288 + n2], acc);
        acc = fmaf(w2, f[2 * 12288 + n2], acc);
        acc = fmaf(w3, f[3 * 12288 + n2], acc);
        acc = fmaf(w4, f[4 * 12288 + n2], acc);
        acc = fmaf(w5, f[5 * 12288 + n2], acc);
        float v = fmaxf(acc, 0.2f * acc);     // leaky relu 0.2
        mx = fmaxf(mx, v);
    }
    red[sub][o] = mx;
    __syncthreads();
    if (sub == 0) {
        float r = fmaxf(fmaxf(red[0][o], red[1][o]), fmaxf(red[2][o], red[3][o]));
        ((float*)g_pmax4)[(b * 192 + o * 3 + kk) * 16 + ch] = r;
    }
}

// ---------------------------------------------------------------------------
// Kernel 3: tail — 1024 threads, PDL-dependent on conv; weight prefetch
// overlaps conv execution. grid 8 (batch), block 1024
// ---------------------------------------------------------------------------
__device__ __forceinline__ void small_knn6(const float* Xin, float* F, int n) {
    float a0 = Xin[n], a1 = Xin[6 + n], a2 = Xin[12 + n];
    Top3 t; t.s0 = t.s1 = t.s2 = -INFINITY; t.i0 = t.i1 = t.i2 = 0;
    for (int m = 0; m < 6; m++) {
        float z0 = Xin[m], z1 = Xin[6 + m], z2 = Xin[12 + m];
        float s = 2.0f * (a0 * z0 + a1 * z1 + a2 * z2) - (z0 * z0 + z1 * z1 + z2 * z2);
        top3_insert(t, s, m);
    }
    int idx3[3] = { t.i0, t.i1, t.i2 };
    for (int kk = 0; kk < 3; kk++) {
        int m = idx3[kk];
        for (int c = 0; c < 3; c++) {
            F[n * 18 + kk * 6 + c] = Xin[m * 3 + c] - Xin[n * 3 + c];
            F[n * 18 + kk * 6 + 3 + c] = Xin[n * 3 + c];
        }
    }
}

__global__ void __launch_bounds__(1024)
tail_kernel(const float* __restrict__ wA, const float* __restrict__ bA,
            const float* __restrict__ wB, const float* __restrict__ bB,
            const float* __restrict__ wC, const float* __restrict__ bC,
            const float* __restrict__ bnAg, const float* __restrict__ bnAb,
            const float* __restrict__ bnAm, const float* __restrict__ bnAv,
            const float* __restrict__ bnBg, const float* __restrict__ bnBb,
            const float* __restrict__ bnBm, const float* __restrict__ bnBv,
            float* __restrict__ out) {
    __shared__ float X1[192], F2[1152], X2[18], F3[108], X3[18], F4[108], X4[18];
    __shared__ float P[82], HA[256], HB[128], LG[3];
    int b = blockIdx.x, t = threadIdx.x;
    int warp = t >> 5, lane = t & 31;

    // independent prelude: prefetch ALL weights while conv is still running
    {
        float p0 = 0.f, p1 = 0.f;
        for (int i = t; i < 20992; i += 1024) p0 += wA[i];          // 256*82
        for (int i = t; i < 32768; i += 1024) p1 += wB[i];          // 128*256
        if (t < 384) p0 += wC[t];
        if (t < 256) p0 += bA[t] + bnAg[t] + bnAb[t] + bnAm[t] + bnAv[t];
        if (t < 128) p1 += bB[t] + bnBg[t] + bnBb[t] + bnBm[t] + bnBv[t];
        if (t < 3)   p1 += bC[t];
        float pf = p0 + p1;
        asm volatile("" :: "f"(pf));
    }

    pdl_wait();                // g_pmax4 now visible

    // reduce partial maxes -> x1 (B,64,3) flat = X1[o*3+kk]; coalesced float4 loads
    if (t < 192) {
        const float4* pm = g_pmax4 + (b * 192 + t) * 4;
        float4 v0 = pm[0], v1 = pm[1], v2 = pm[2], v3 = pm[3];
        float m0 = fmaxf(fmaxf(v0.x, v0.y), fmaxf(v0.z, v0.w));
        float m1 = fmaxf(fmaxf(v1.x, v1.y), fmaxf(v1.z, v1.w));
        float m2 = fmaxf(fmaxf(v2.x, v2.y), fmaxf(v2.z, v2.w));
        float m3 = fmaxf(fmaxf(v3.x, v3.y), fmaxf(v3.z, v3.w));
        X1[t] = fmaxf(fmaxf(m0, m1), fmaxf(m2, m3));
    }
    __syncthreads();

    // stage 2: kNN on 64 points, z[c][m] = X1[c*64+m], P[n][c] = X1[n*3+c]
    if (t < 64) {
        int n = t;
        float a0 = X1[n], a1 = X1[64 + n], a2 = X1[128 + n];
        Top3 tp; tp.s0 = tp.s1 = tp.s2 = -INFINITY; tp.i0 = tp.i1 = tp.i2 = 0;
        for (int m = 0; m < 64; m++) {
            float z0 = X1[m], z1 = X1[64 + m], z2 = X1[128 + m];
            float s = 2.0f * (a0 * z0 + a1 * z1 + a2 * z2) - (z0 * z0 + z1 * z1 + z2 * z2);
            top3_insert(tp, s, m);
        }
        int idx3[3] = { tp.i0, tp.i1, tp.i2 };
        for (int kk = 0; kk < 3; kk++) {
            int m = idx3[kk];
            for (int c = 0; c < 3; c++) {
                F2[n * 18 + kk * 6 + c] = X1[m * 3 + c] - X1[n * 3 + c];
                F2[n * 18 + kk * 6 + 3 + c] = X1[n * 3 + c];
            }
        }
    }
    __syncthreads();
    if (t < 18) {   // max over 64 consecutive (flat-reshape semantics)
        float mx = -INFINITY;
        for (int j = 0; j < 64; j++) mx = fmaxf(mx, F2[t * 64 + j]);
        X2[t] = mx;
    }
    __syncthreads();

    if (t < 6) small_knn6(X2, F3, t);
    __syncthreads();
    if (t < 18) {
        float mx = -INFINITY;
        for (int j = 0; j < 6; j++) mx = fmaxf(mx, F3[t * 6 + j]);
        X3[t] = mx;
    }
    __syncthreads();

    if (t < 6) small_knn6(X3, F4, t);
    __syncthreads();
    if (t < 18) {
        float mx = -INFINITY;
        for (int j = 0; j < 6; j++) mx = fmaxf(mx, F4[t * 6 + j]);
        X4[t] = mx;
    }
    __syncthreads();

    // pool: p[82] = max over last axis of concat([x1, x2, x3, x4], axis=1)
    if (t < 82) {
        float mx;
        if (t < 64)      mx = fmaxf(fmaxf(X1[t * 3], X1[t * 3 + 1]), X1[t * 3 + 2]);
        else if (t < 70) { int c = t - 64; mx = fmaxf(fmaxf(X2[c * 3], X2[c * 3 + 1]), X2[c * 3 + 2]); }
        else if (t < 76) { int c = t - 70; mx = fmaxf(fmaxf(X3[c * 3], X3[c * 3 + 1]), X3[c * 3 + 2]); }
        else             { int c = t - 76; mx = fmaxf(fmaxf(X4[c * 3], X4[c * 3 + 1]), X4[c * 3 + 2]); }
        P[t] = mx;
    }
    __syncthreads();

    // MLP A: 82 -> 256, 32 warps x 8 outputs, lanes coalesced over inputs
#pragma unroll
    for (int rep = 0; rep < 8; rep++) {
        int j = warp * 8 + rep;
        const float* wr = wA + j * 82;
        float acc = P[lane] * wr[lane];
        acc = fmaf(P[lane + 32], wr[lane + 32], acc);
        if (lane < 18) acc = fmaf(P[lane + 64], wr[lane + 64], acc);
#pragma unroll
        for (int d = 16; d > 0; d >>= 1)
            acc += __shfl_xor_sync(0xFFFFFFFFu, acc, d);
        if (lane == 0) {
            acc += bA[j];
            float s = bnAg[j] / sqrtf(bnAv[j] + EPS);
            acc = (acc - bnAm[j]) * s + bnAb[j];
            HA[j] = fmaxf(acc, 0.2f * acc);
        }
    }
    __syncthreads();

    // MLP B: 256 -> 128, 32 warps x 4 outputs
#pragma unroll
    for (int rep = 0; rep < 4; rep++) {
        int j = warp * 4 + rep;
        const float* wr = wB + j * 256;
        float a0 = HA[lane] * wr[lane];
        float a1 = HA[lane + 32] * wr[lane + 32];
#pragma unroll
        for (int e = 2; e < 8; e += 2) {
            a0 = fmaf(HA[lane + 32 * e], wr[lane + 32 * e], a0);
            a1 = fmaf(HA[lane + 32 * (e + 1)], wr[lane + 32 * (e + 1)], a1);
        }
        float acc = a0 + a1;
#pragma unroll
        for (int d = 16; d > 0; d >>= 1)
            acc += __shfl_xor_sync(0xFFFFFFFFu, acc, d);
        if (lane == 0) {
            acc += bB[j];
            float s = bnBg[j] / sqrtf(bnBv[j] + EPS);
            acc = (acc - bnBm[j]) * s + bnBb[j];
            HB[j] = fmaxf(acc, 0.2f * acc);
        }
    }
    __syncthreads();

    // MLP C: 128 -> 3 via warp-shuffle reduction (warps 0-2)
    if (t < 96) {
        int o = warp, l = lane;
        float acc = 0.0f;
#pragma unroll
        for (int e = 0; e < 4; e++) {
            int i = l + 32 * e;
            acc = fmaf(HB[i], wC[o * 128 + i], acc);
        }
#pragma unroll
        for (int d = 16; d > 0; d >>= 1)
            acc += __shfl_xor_sync(0xFFFFFFFFu, acc, d);
        if (l == 0) LG[o] = acc + bC[o];
    }
    __syncthreads();
    if (t == 0) {
        float m = fmaxf(fmaxf(LG[0], LG[1]), LG[2]);
        float e0 = expf(LG[0] - m), e1 = expf(LG[1] - m), e2 = expf(LG[2] - m);
        float inv = 1.0f / (e0 + e1 + e2);
        out[b * 3 + 0] = e0 * inv;
        out[b * 3 + 1] = e1 * inv;
        out[b * 3 + 2] = e2 * inv;
    }
}

// ---------------------------------------------------------------------------
extern "C" void kernel_launch(void* const* d_in, const int* in_sizes, int n_in,
                              void* d_out, int out_size) {
    const float* x   = (const float*)d_in[0];
    const float* w1  = (const float*)d_in[1];
    const float* wA  = (const float*)d_in[2];
    const float* bA  = (const float*)d_in[3];
    const float* wB  = (const float*)d_in[4];
    const float* bB  = (const float*)d_in[5];
    const float* wC  = (const float*)d_in[6];
    const float* bC  = (const float*)d_in[7];
    const float* bn1g = (const float*)d_in[8];
    const float* bn1b = (const float*)d_in[9];
    const float* bn1m = (const float*)d_in[10];
    const float* bn1v = (const float*)d_in[11];
    const float* bnAg = (const float*)d_in[12];
    const float* bnAb = (const float*)d_in[13];
    const float* bnAm = (const float*)d_in[14];
    const float* bnAv = (const float*)d_in[15];
    const float* bnBg = (const float*)d_in[16];
    const float* bnBb = (const float*)d_in[17];
    const float* bnBm = (const float*)d_in[18];
    const float* bnBv = (const float*)d_in[19];

    // K1: normal launch
    knn_partial_kernel<<<dim3(8, 8, NQ), 256>>>(x);

    // K2..K4: PDL launches (overlap launch latency with predecessor execution)
    cudaLaunchAttribute attrs[1];
    attrs[0].id = cudaLaunchAttributeProgrammaticStreamSerialization;
    attrs[0].val.programmaticStreamSerializationAllowed = 1;

    {
        cudaLaunchConfig_t cfg = {};
        cfg.gridDim = dim3(16, 8);
        cfg.blockDim = dim3(256);
        cfg.dynamicSmemBytes = 0;
        cfg.stream = 0;
        cfg.attrs = attrs;
        cfg.numAttrs = 1;
        cudaLaunchKernelEx(&cfg, knn_merge_kernel, x);
    }
    {
        cudaLaunchConfig_t cfg = {};
        cfg.gridDim = dim3(384);
        cfg.blockDim = dim3(256);
        cfg.dynamicSmemBytes = 0;
        cfg.stream = 0;
        cfg.attrs = attrs;
        cfg.numAttrs = 1;
        cudaLaunchKernelEx(&cfg, conv_max_kernel, w1, bn1g, bn1b, bn1m, bn1v);
    }
    {
        cudaLaunchConfig_t cfg = {};
        cfg.gridDim = dim3(8);
        cfg.blockDim = dim3(1024);
        cfg.dynamicSmemBytes = 0;
        cfg.stream = 0;
        cfg.attrs = attrs;
        cfg.numAttrs = 1;
        cudaLaunchKernelEx(&cfg, tail_kernel, wA, bA, wB, bB, wC, bC,
                           bnAg, bnAb, bnAm, bnAv,
                           bnBg, bnBb, bnBm, bnBv,
                           (float*)d_out);
    }
}